// round 5
// baseline (speedup 1.0000x reference)
#include <cuda_runtime.h>
#include <cuda_bf16.h>

#define NJ 24
#define EPSF 1e-6f

__device__ __forceinline__ float sqrt_ap(float x) {
    float r; asm("sqrt.approx.f32 %0, %1;" : "=f"(r) : "f"(x)); return r;
}
__device__ __forceinline__ float rcp_ap(float x) {
    float r; asm("rcp.approx.f32 %0, %1;" : "=f"(r) : "f"(x)); return r;
}

// Shared layout per joint (6 float4 = 24 floats):
//  [0] m00 m01 m02 m03
//  [1] m10 m11 m12 m13
//  [2] m20 m21 m22 m23
//  [3] lx  ly  lz  a0'   (a0' = C0*f0 + 0.5 - C2c*f6)
//  [4] a1  a2  a3  a4    (a1=-C1*f1, a2=C1*f2, a3=-C1*f3, a4=B*f4)
//  [5] a5  b6  a7  a8    (a5=-B*f5, b6=3*C2c*f6, a7=-B*f7, a8=D*f8)

__global__ __launch_bounds__(256)
void shCaster_kernel(const float* __restrict__ xyz,
                     const float* __restrict__ vdir,
                     const float* __restrict__ transforms,
                     const float* __restrict__ sh_feats,
                     const float* __restrict__ locs,
                     float* __restrict__ out,
                     int n)
{
    __shared__ __align__(16) float4 S[NJ * 6];

    {
        float* Sf = reinterpret_cast<float*>(S);
        const float coef0 = 0.28209479177387814f;
        const float coefA = 0.4886025119029199f;
        const float coefB = 1.0925484305920792f;
        const float coefC = 0.31539156525252005f;
        const float coefD = 0.5462742152960396f;
        for (int idx = threadIdx.x; idx < NJ * 24; idx += blockDim.x) {
            int j = idx / 24, k = idx % 24;
            float v;
            if (k < 12) {
                v = transforms[j * 16 + k];
            } else if (k < 15) {
                v = locs[j * 3 + (k - 12)];
            } else if (k == 15) {
                v = coef0 * sh_feats[j * 9 + 0] + 0.5f - coefC * sh_feats[j * 9 + 6];
            } else if (k == 16) {
                v = -coefA * sh_feats[j * 9 + 1];
            } else if (k == 17) {
                v =  coefA * sh_feats[j * 9 + 2];
            } else if (k == 18) {
                v = -coefA * sh_feats[j * 9 + 3];
            } else if (k == 19) {
                v =  coefB * sh_feats[j * 9 + 4];
            } else if (k == 20) {
                v = -coefB * sh_feats[j * 9 + 5];
            } else if (k == 21) {
                v = 3.0f * coefC * sh_feats[j * 9 + 6];
            } else if (k == 22) {
                v = -coefB * sh_feats[j * 9 + 7];
            } else {
                v =  coefD * sh_feats[j * 9 + 8];
            }
            Sf[j * 24 + k] = v;
        }
    }
    __syncthreads();

    int i = blockIdx.x * blockDim.x + threadIdx.x;
    if (i >= n) return;

    const float x = __ldg(&xyz[3 * i]);
    const float y = __ldg(&xyz[3 * i + 1]);
    const float z = __ldg(&xyz[3 * i + 2]);

    float wsum = 0.f;
    float ox = 0.f, oy = 0.f, oz = 0.f;
    // accumulated rotation matrix  Sum_j w_j * R_j
    float t00 = 0.f, t01 = 0.f, t02 = 0.f;
    float t10 = 0.f, t11 = 0.f, t12 = 0.f;
    float t20 = 0.f, t21 = 0.f, t22 = 0.f;

#pragma unroll
    for (int j = 0; j < NJ; ++j) {
        const float4 m0  = S[j * 6 + 0];
        const float4 m1  = S[j * 6 + 1];
        const float4 m2  = S[j * 6 + 2];
        const float4 lc  = S[j * 6 + 3];
        const float4 cA  = S[j * 6 + 4];
        const float4 cB  = S[j * 6 + 5];

        // p = (M [x,1])[:3]
        float px = fmaf(m0.x, x, fmaf(m0.y, y, fmaf(m0.z, z, m0.w)));
        float py = fmaf(m1.x, x, fmaf(m1.y, y, fmaf(m1.z, z, m1.w)));
        float pz = fmaf(m2.x, x, fmaf(m2.y, y, fmaf(m2.z, z, m2.w)));

        // d = loc - p
        float dx = lc.x - px, dy = lc.y - py, dz = lc.z - pz;

        float sx = dx * dx, sy = dy * dy, sz = dz * dz;
        float n2 = (sx + sy) + sz;

        // linear SH on d:  L = a1*dy + a2*dz + a3*dx
        float L = fmaf(cA.x, dy, fmaf(cA.y, dz, cA.z * dx));

        // quadratic SH on d:  Q = a4*dxdy + a5*dydz + b6*dz^2 + a7*dxdz + a8*(dx^2-dy^2)
        float Q = cA.w * (dx * dy);
        Q = fmaf(cB.x, dy * dz, Q);
        Q = fmaf(cB.y, sz, Q);
        Q = fmaf(cB.z, dx * dz, Q);
        Q = fmaf(cB.w, sx - sy, Q);

        float s = sqrt_ap(n2);

        // denom = rad*n2 = a0'*n2 + L*s + Q ;  numer = len*n2 = n2*s
        float denom = fmaf(lc.w, n2, Q);
        denom = fmaf(L, s, denom);
        float tt = fmaf(-n2, s, denom);          // denom - numer

        // w = relu(denom-numer)/denom  (0 whenever rad <= 0, incl. rad < EPS cases)
        float w = fmaxf(tt, 0.f) * rcp_ap(fmaxf(denom, 1e-30f));

        wsum += w;
        ox = fmaf(w, px, ox);
        oy = fmaf(w, py, oy);
        oz = fmaf(w, pz, oz);

        t00 = fmaf(w, m0.x, t00);
        t01 = fmaf(w, m0.y, t01);
        t02 = fmaf(w, m0.z, t02);
        t10 = fmaf(w, m1.x, t10);
        t11 = fmaf(w, m1.y, t11);
        t12 = fmaf(w, m1.z, t12);
        t20 = fmaf(w, m2.x, t20);
        t21 = fmaf(w, m2.y, t21);
        t22 = fmaf(w, m2.z, t22);
    }

    const float vx = __ldg(&vdir[3 * i]);
    const float vy = __ldg(&vdir[3 * i + 1]);
    const float vz = __ldg(&vdir[3 * i + 2]);

    float* outv = out + (size_t)3 * n;

    if (wsum > EPSF) {
        float inv = rcp_ap(wsum);
        out[3 * i]     = ox * inv;
        out[3 * i + 1] = oy * inv;
        out[3 * i + 2] = oz * inv;
        // view_out = (Sum w R_j) @ v / wsum
        outv[3 * i]     = fmaf(t00, vx, fmaf(t01, vy, t02 * vz)) * inv;
        outv[3 * i + 1] = fmaf(t10, vx, fmaf(t11, vy, t12 * vz)) * inv;
        outv[3 * i + 2] = fmaf(t20, vx, fmaf(t21, vy, t22 * vz)) * inv;
    } else {
        out[3 * i]     = x;
        out[3 * i + 1] = y;
        out[3 * i + 2] = z;
        outv[3 * i]     = vx;
        outv[3 * i + 1] = vy;
        outv[3 * i + 2] = vz;
    }
}

extern "C" void kernel_launch(void* const* d_in, const int* in_sizes, int n_in,
                              void* d_out, int out_size) {
    const float* xyz        = (const float*)d_in[0];
    const float* viewdirs   = (const float*)d_in[1];
    const float* transforms = (const float*)d_in[2];
    // d_in[3] = ray_valid — unused
    const float* sh_feats   = (const float*)d_in[4];
    const float* locs       = (const float*)d_in[5];
    float* out = (float*)d_out;

    int n = in_sizes[0] / 3;      // 524288
    int threads = 256;
    int blocks = (n + threads - 1) / threads;
    shCaster_kernel<<<blocks, threads>>>(xyz, viewdirs, transforms, sh_feats,
                                         locs, out, n);
}

// round 8
// speedup vs baseline: 1.0494x; 1.0494x over previous
#include <cuda_runtime.h>
#include <cuda_bf16.h>

#define NJ 24
#define EPSF 1e-6f

typedef unsigned long long ull;

// ---- packed f32x2 helpers (sm_103a) ----
__device__ __forceinline__ ull f2_fma(ull a, ull b, ull c) {
    ull d; asm("fma.rn.f32x2 %0, %1, %2, %3;" : "=l"(d) : "l"(a), "l"(b), "l"(c)); return d;
}
__device__ __forceinline__ ull f2_mul(ull a, ull b) {
    ull d; asm("mul.rn.f32x2 %0, %1, %2;" : "=l"(d) : "l"(a), "l"(b)); return d;
}
__device__ __forceinline__ ull f2_add(ull a, ull b) {
    ull d; asm("add.rn.f32x2 %0, %1, %2;" : "=l"(d) : "l"(a), "l"(b)); return d;
}
__device__ __forceinline__ ull f2_pack(float lo, float hi) {
    ull d;
    asm("mov.b64 %0, {%1, %2};" : "=l"(d) : "r"(__float_as_uint(lo)), "r"(__float_as_uint(hi)));
    return d;
}
__device__ __forceinline__ void f2_unpack(ull a, float& lo, float& hi) {
    unsigned int l, h;
    asm("mov.b64 {%0, %1}, %2;" : "=r"(l), "=r"(h) : "l"(a));
    lo = __uint_as_float(l); hi = __uint_as_float(h);
}
__device__ __forceinline__ float sqrt_ap(float x) {
    float r; asm("sqrt.approx.f32 %0, %1;" : "=f"(r) : "f"(x)); return r;
}
__device__ __forceinline__ float rcp_ap(float x) {
    float r; asm("rcp.approx.f32 %0, %1;" : "=f"(r) : "f"(x)); return r;
}

// Shared layout per joint: 24 duplicated {c,c} pairs (12 x ulonglong2):
//  pair 0..5  : transform rows 0..2 (m00 m01 | m02 m03 | m10 m11 | m12 m13 | m20 m21 | m22 m23)
//  pair 6,7   : lx ly | lz a0'   (a0' = C0*f0 + 0.5 - C2c*f6)
//  pair 8,9   : a1 a2 | a3 a4
//  pair 10,11 : a5 b6 | a7 a8
__global__ __launch_bounds__(256)
void shCaster_kernel(const float* __restrict__ xyz,
                     const float* __restrict__ vdir,
                     const float* __restrict__ transforms,
                     const float* __restrict__ sh_feats,
                     const float* __restrict__ locs,
                     float* __restrict__ out,
                     int half, int n)
{
    __shared__ __align__(16) ull S2[NJ * 24];

    {
        const float coef0 = 0.28209479177387814f;
        const float coefA = 0.4886025119029199f;
        const float coefB = 1.0925484305920792f;
        const float coefC = 0.31539156525252005f;
        const float coefD = 0.5462742152960396f;
        for (int idx = threadIdx.x; idx < NJ * 24; idx += blockDim.x) {
            int j = idx / 24, k = idx % 24;
            float v;
            if (k < 12) {
                v = transforms[j * 16 + k];
            } else if (k < 15) {
                v = locs[j * 3 + (k - 12)];
            } else if (k == 15) {
                v = coef0 * sh_feats[j * 9 + 0] + 0.5f - coefC * sh_feats[j * 9 + 6];
            } else if (k == 16) {
                v = -coefA * sh_feats[j * 9 + 1];
            } else if (k == 17) {
                v =  coefA * sh_feats[j * 9 + 2];
            } else if (k == 18) {
                v = -coefA * sh_feats[j * 9 + 3];
            } else if (k == 19) {
                v =  coefB * sh_feats[j * 9 + 4];
            } else if (k == 20) {
                v = -coefB * sh_feats[j * 9 + 5];
            } else if (k == 21) {
                v = 3.0f * coefC * sh_feats[j * 9 + 6];
            } else if (k == 22) {
                v = -coefB * sh_feats[j * 9 + 7];
            } else {
                v =  coefD * sh_feats[j * 9 + 8];
            }
            unsigned int b = __float_as_uint(v);
            S2[j * 24 + k] = ((ull)b << 32) | b;
        }
    }
    __syncthreads();

    int t = blockIdx.x * blockDim.x + threadIdx.x;
    if (t >= half) return;
    int i0 = t, i1 = t + half;

    const ull x2 = f2_pack(__ldg(&xyz[3 * i0]),     __ldg(&xyz[3 * i1]));
    const ull y2 = f2_pack(__ldg(&xyz[3 * i0 + 1]), __ldg(&xyz[3 * i1 + 1]));
    const ull z2 = f2_pack(__ldg(&xyz[3 * i0 + 2]), __ldg(&xyz[3 * i1 + 2]));

    const ull NEG1 = f2_pack(-1.f, -1.f);

    ull wsum2 = 0ull;
    // accumulated affine matrix Sum_j w_j * [R_j | tr_j]  (3x4, packed pairs)
    ull t00 = 0ull, t01 = 0ull, t02 = 0ull, t03 = 0ull;
    ull t10 = 0ull, t11 = 0ull, t12 = 0ull, t13 = 0ull;
    ull t20 = 0ull, t21 = 0ull, t22 = 0ull, t23 = 0ull;

    const ulonglong2* __restrict__ Cbase =
        reinterpret_cast<const ulonglong2*>(S2);

#pragma unroll 4
    for (int j = 0; j < NJ; ++j) {
        const ulonglong2* C = Cbase + j * 12;
        const ulonglong2 c0 = C[0];
        const ulonglong2 c1 = C[1];
        const ulonglong2 c2 = C[2];
        const ulonglong2 c3 = C[3];
        const ulonglong2 c4 = C[4];
        const ulonglong2 c5 = C[5];
        const ulonglong2 c6 = C[6];
        const ulonglong2 c7 = C[7];
        const ulonglong2 c8 = C[8];
        const ulonglong2 c9 = C[9];
        const ulonglong2 cA = C[10];
        const ulonglong2 cB = C[11];

        // p = (M [x,1])[:3] ; d = loc - p  (p dies immediately)
        ull px = f2_fma(c0.x, x2, f2_fma(c0.y, y2, f2_fma(c1.x, z2, c1.y)));
        ull py = f2_fma(c2.x, x2, f2_fma(c2.y, y2, f2_fma(c3.x, z2, c3.y)));
        ull pz = f2_fma(c4.x, x2, f2_fma(c4.y, y2, f2_fma(c5.x, z2, c5.y)));
        ull dx = f2_fma(px, NEG1, c6.x);
        ull dy = f2_fma(py, NEG1, c6.y);
        ull dz = f2_fma(pz, NEG1, c7.x);

        ull sx = f2_mul(dx, dx);
        ull sy = f2_mul(dy, dy);
        ull sz = f2_mul(dz, dz);
        ull n2 = f2_add(f2_add(sx, sy), sz);

        // linear SH on d
        ull L = f2_fma(c8.x, dy, f2_fma(c8.y, dz, f2_mul(c9.x, dx)));

        // quadratic SH on d
        ull Q = f2_mul(c9.y, f2_mul(dx, dy));
        Q = f2_fma(cA.x, f2_mul(dy, dz), Q);
        Q = f2_fma(cA.y, sz, Q);
        Q = f2_fma(cB.x, f2_mul(dx, dz), Q);
        Q = f2_fma(cB.y, f2_fma(sy, NEG1, sx), Q);

        // s = sqrt(n2) per lane
        float n2a, n2b; f2_unpack(n2, n2a, n2b);
        ull s2 = f2_pack(sqrt_ap(n2a), sqrt_ap(n2b));

        // denom = rad*n2 = a0'*n2 + L*s + Q ; numer = n2*s
        ull denom = f2_fma(c7.y, n2, Q);
        denom = f2_fma(L, s2, denom);
        ull tt = f2_fma(f2_mul(n2, s2), NEG1, denom);   // denom - numer

        // w = relu(denom-numer)/denom  (scalar relu/guard)
        float ta, tb; f2_unpack(tt, ta, tb);
        float da, db; f2_unpack(denom, da, db);
        float wa = fmaxf(ta, 0.f) * rcp_ap(fmaxf(da, 1e-30f));
        float wb = fmaxf(tb, 0.f) * rcp_ap(fmaxf(db, 1e-30f));
        ull w2 = f2_pack(wa, wb);

        wsum2 = f2_add(wsum2, w2);
        t00 = f2_fma(w2, c0.x, t00);
        t01 = f2_fma(w2, c0.y, t01);
        t02 = f2_fma(w2, c1.x, t02);
        t03 = f2_fma(w2, c1.y, t03);
        t10 = f2_fma(w2, c2.x, t10);
        t11 = f2_fma(w2, c2.y, t11);
        t12 = f2_fma(w2, c3.x, t12);
        t13 = f2_fma(w2, c3.y, t13);
        t20 = f2_fma(w2, c4.x, t20);
        t21 = f2_fma(w2, c4.y, t21);
        t22 = f2_fma(w2, c5.x, t22);
        t23 = f2_fma(w2, c5.y, t23);
    }

    // ---- epilogue (per lane) ----
    const float vxa = __ldg(&vdir[3 * i0]),     vxb = __ldg(&vdir[3 * i1]);
    const float vya = __ldg(&vdir[3 * i0 + 1]), vyb = __ldg(&vdir[3 * i1 + 1]);
    const float vza = __ldg(&vdir[3 * i0 + 2]), vzb = __ldg(&vdir[3 * i1 + 2]);

    float wsa, wsb; f2_unpack(wsum2, wsa, wsb);
    float a00, b00; f2_unpack(t00, a00, b00);
    float a01, b01; f2_unpack(t01, a01, b01);
    float a02, b02; f2_unpack(t02, a02, b02);
    float a03, b03; f2_unpack(t03, a03, b03);
    float a10, b10; f2_unpack(t10, a10, b10);
    float a11, b11; f2_unpack(t11, a11, b11);
    float a12, b12; f2_unpack(t12, a12, b12);
    float a13, b13; f2_unpack(t13, a13, b13);
    float a20, b20; f2_unpack(t20, a20, b20);
    float a21, b21; f2_unpack(t21, a21, b21);
    float a22, b22; f2_unpack(t22, a22, b22);
    float a23, b23; f2_unpack(t23, a23, b23);

    float xa, xb, ya, yb, za, zb;
    f2_unpack(x2, xa, xb); f2_unpack(y2, ya, yb); f2_unpack(z2, za, zb);

    float* outv = out + (size_t)3 * n;

    if (wsa > EPSF) {
        float inv = rcp_ap(wsa);
        out[3 * i0]     = fmaf(a00, xa, fmaf(a01, ya, fmaf(a02, za, a03))) * inv;
        out[3 * i0 + 1] = fmaf(a10, xa, fmaf(a11, ya, fmaf(a12, za, a13))) * inv;
        out[3 * i0 + 2] = fmaf(a20, xa, fmaf(a21, ya, fmaf(a22, za, a23))) * inv;
        outv[3 * i0]     = fmaf(a00, vxa, fmaf(a01, vya, a02 * vza)) * inv;
        outv[3 * i0 + 1] = fmaf(a10, vxa, fmaf(a11, vya, a12 * vza)) * inv;
        outv[3 * i0 + 2] = fmaf(a20, vxa, fmaf(a21, vya, a22 * vza)) * inv;
    } else {
        out[3 * i0] = xa;  out[3 * i0 + 1] = ya;  out[3 * i0 + 2] = za;
        outv[3 * i0] = vxa; outv[3 * i0 + 1] = vya; outv[3 * i0 + 2] = vza;
    }
    if (wsb > EPSF) {
        float inv = rcp_ap(wsb);
        out[3 * i1]     = fmaf(b00, xb, fmaf(b01, yb, fmaf(b02, zb, b03))) * inv;
        out[3 * i1 + 1] = fmaf(b10, xb, fmaf(b11, yb, fmaf(b12, zb, b13))) * inv;
        out[3 * i1 + 2] = fmaf(b20, xb, fmaf(b21, yb, fmaf(b22, zb, b23))) * inv;
        outv[3 * i1]     = fmaf(b00, vxb, fmaf(b01, vyb, b02 * vzb)) * inv;
        outv[3 * i1 + 1] = fmaf(b10, vxb, fmaf(b11, vyb, b12 * vzb)) * inv;
        outv[3 * i1 + 2] = fmaf(b20, vxb, fmaf(b21, vyb, b22 * vzb)) * inv;
    } else {
        out[3 * i1] = xb;  out[3 * i1 + 1] = yb;  out[3 * i1 + 2] = zb;
        outv[3 * i1] = vxb; outv[3 * i1 + 1] = vyb; outv[3 * i1 + 2] = vzb;
    }
}

extern "C" void kernel_launch(void* const* d_in, const int* in_sizes, int n_in,
                              void* d_out, int out_size) {
    const float* xyz        = (const float*)d_in[0];
    const float* viewdirs   = (const float*)d_in[1];
    const float* transforms = (const float*)d_in[2];
    // d_in[3] = ray_valid — unused
    const float* sh_feats   = (const float*)d_in[4];
    const float* locs       = (const float*)d_in[5];
    float* out = (float*)d_out;

    int n = in_sizes[0] / 3;      // 524288
    int half = n / 2;             // 262144
    int threads = 256;
    int blocks = (half + threads - 1) / threads;
    shCaster_kernel<<<blocks, threads>>>(xyz, viewdirs, transforms, sh_feats,
                                         locs, out, half, n);
}